// round 2
// baseline (speedup 1.0000x reference)
#include <cuda_runtime.h>
#include <cstdint>

#define Hh 128
#define Ww 128
#define LL 16384          // H*W
#define NB 2
#define NC1 64
#define NC2 128
#define OUT_LV2_ELEMS 4194304

// Scratch
__device__ int    g_idx[NB * LL];                    // 128 KB
__device__ int    g_stride;                          // 1 = int32 input, 2 = int64 input
__device__ float4 g_blk2[(size_t)NB * LL * NC1];     // 33.5 MB: [b][cell][c] -> 2x2 block

// ---------------------------------------------------------------------------
// Detect index dtype (jax may canonicalize int64->int32). Values < 16384, so
// for an int64 buffer every odd 32-bit word is 0. Sampling 2048 odd words of
// an int32 buffer of uniform random values is all-zero with prob ~0.
// ---------------------------------------------------------------------------
__global__ void k_detect(const int* __restrict__ hw) {
    __shared__ int s_or;
    if (threadIdx.x == 0) s_or = 0;
    __syncthreads();
    int acc = 0;
    for (int i = threadIdx.x; i < 2048; i += blockDim.x) acc |= hw[2 * i + 1];
    if (acc) atomicOr(&s_or, 1);
    __syncthreads();
    if (threadIdx.x == 0) g_stride = s_or ? 1 : 2;
}

__global__ void k_extract(const int* __restrict__ hw) {
    int stride = g_stride;
    int i = blockIdx.x * blockDim.x + threadIdx.x;
    if (i < NB * LL) g_idx[i] = hw[i * stride];
}

// ---------------------------------------------------------------------------
// k_blk: space-to-depth transpose of lv1 into channel-innermost layout.
// g_blk2[(b*LL + cell)*64 + c] = float4{p00,p01,p10,p11} of channel c's 2x2
// block at coarse cell. Block = (b, mh, 32-cell v-tile); SMEM-staged so both
// global reads and global writes are coalesced.
// ---------------------------------------------------------------------------
__global__ void k_blk(const float* __restrict__ lv1) {
    __shared__ float4 s4[64 * 33];            // [c][vl] padded (stride 33 f4)
    float* s = (float*)s4;
    int bid = blockIdx.x;                     // 2*128*4 = 1024
    int vt = bid & 3;
    int mh = (bid >> 2) & 127;
    int b  = bid >> 9;
    int v0 = vt << 5;

    // Read phase: 2048 float4 (64 ch x 2 rows x 64 cols), coalesced.
#pragma unroll
    for (int k = 0; k < 8; k++) {
        int j  = threadIdx.x + (k << 8);
        int c  = j >> 5;
        int dy = (j >> 4) & 1;
        int x4 = j & 15;
        const float4 val = *(const float4*)(lv1 + (((size_t)(b * NC1 + c)) << 16)
                                            + ((2 * mh + dy) << 8) + (v0 << 1) + (x4 << 2));
        int vl0 = x4 << 1;                    // covers cells vl0, vl0+1
        float* pc = s + c * 132;              // 132 floats per c (33 f4)
        pc[(vl0    ) * 4 + dy * 2 + 0] = val.x;
        pc[(vl0    ) * 4 + dy * 2 + 1] = val.y;
        pc[(vl0 + 1) * 4 + dy * 2 + 0] = val.z;
        pc[(vl0 + 1) * 4 + dy * 2 + 1] = val.w;
    }
    __syncthreads();

    // Write phase: g_blk2[b][mh*128 + v0 + vl][c], lanes over c -> 512B/warp.
    float4* dst = g_blk2 + ((size_t)b * LL + (mh << 7) + v0) * 64;
#pragma unroll
    for (int k = 0; k < 8; k++) {
        int j  = threadIdx.x + (k << 8);
        int vl = j >> 6;
        int c  = j & 63;
        dst[(size_t)vl * 64 + c] = s4[c * 33 + vl];
    }
}

// ---------------------------------------------------------------------------
// k_lv2: unchanged — plane-resident SMEM gather (2 channels/block, 128KB).
// ---------------------------------------------------------------------------
__global__ void k_lv2(const float* __restrict__ lv2, float* __restrict__ out) {
    extern __shared__ float2 s_plane[];
    int bcp = blockIdx.x;
    int cp  = bcp & 63;
    int b   = bcp >> 6;
    const float* base0 = lv2 + ((size_t)(b * NC2 + cp * 2) << 14);
    for (int i = threadIdx.x; i < LL; i += blockDim.x)
        s_plane[i] = make_float2(base0[i], base0[i + LL]);
    __syncthreads();

    const int* idxb = g_idx + (b << 14);
    float* out0 = out + ((size_t)(b * NC2 + cp * 2) << 14);
    const float inv9 = 1.0f / 9.0f;

    for (int p = threadIdx.x; p < LL; p += blockDim.x) {
        int y = p >> 7, x = p & 127;
        float a0 = 0.f, a1 = 0.f;
#pragma unroll
        for (int dy = -1; dy <= 1; dy++) {
#pragma unroll
            for (int dx = -1; dx <= 1; dx++) {
                int oy = y - dy, ox = x - dx;
                if ((unsigned)oy < Hh && (unsigned)ox < Ww) {
                    int m  = idxb[(oy << 7) + ox];
                    int sr = (m >> 7)  + dy;
                    int sc = (m & 127) + dx;
                    if ((unsigned)sr < Hh && (unsigned)sc < Ww) {
                        float2 v = s_plane[(sr << 7) + sc];
                        a0 += v.x; a1 += v.y;
                    }
                }
            }
        }
        out0[p]      = a0 * inv9;
        out0[p + LL] = a1 * inv9;
    }
}

// ---------------------------------------------------------------------------
// k_lv1: warp-per-cell gather, lanes = channels. Each tap = two coalesced
// 512B LDG.128 (all bytes consumed). Output transposed via padded SMEM so
// global stores are coalesced 512B rows.
// Block = (b, u, 64-cell v-tile); 8 warps x 8 cells.
// ---------------------------------------------------------------------------
__global__ void k_lv1(float* __restrict__ out) {
    extern __shared__ float sh[];             // 128 rows x 132 floats = 67584 B
    int bid = blockIdx.x;                     // 2*128*2 = 512
    int vt = bid & 1;
    int u  = (bid >> 1) & 127;
    int b  = bid >> 8;
    int v0 = vt << 6;
    int w    = threadIdx.x >> 5;
    int lane = threadIdx.x & 31;
    const int*    idxb = g_idx + (b << 14);
    const float4* blkb = g_blk2 + (((size_t)b) << 14) * 64;
    const float inv9 = 1.0f / 9.0f;

    for (int jj = 0; jj < 8; jj++) {
        int j = (w << 3) + jj;                // local cell 0..63
        int v = v0 + j;
        float4 A0 = make_float4(0.f, 0.f, 0.f, 0.f);
        float4 A1 = make_float4(0.f, 0.f, 0.f, 0.f);
#pragma unroll
        for (int dy = -1; dy <= 1; dy++) {
#pragma unroll
            for (int dx = -1; dx <= 1; dx++) {
                int ou = u - dy, ov = v - dx;
                if ((unsigned)ou < Hh && (unsigned)ov < Ww) {
                    int m   = idxb[(ou << 7) + ov];          // uniform across warp
                    int shh = (m >> 7)  + dy;
                    int sww = (m & 127) + dx;
                    if ((unsigned)shh < Hh && (unsigned)sww < Ww) {
                        const float4* q = blkb + (((size_t)((shh << 7) + sww)) << 6);
                        float4 q0 = q[lane];
                        float4 q1 = q[lane + 32];
                        A0.x += q0.x; A0.y += q0.y; A0.z += q0.z; A0.w += q0.w;
                        A1.x += q1.x; A1.y += q1.y; A1.z += q1.z; A1.w += q1.w;
                    }
                }
            }
        }
        // SMEM rows r = py*64 + c (stride 132), cols = 2*j + px
        float* p0 = sh + lane * 132 + (j << 1);           // py0, c=lane
        p0[0] = A0.x * inv9; p0[1] = A0.y * inv9;
        float* p1 = sh + (64 + lane) * 132 + (j << 1);    // py1, c=lane
        p1[0] = A0.z * inv9; p1[1] = A0.w * inv9;
        float* p2 = sh + (lane + 32) * 132 + (j << 1);    // py0, c=lane+32
        p2[0] = A1.x * inv9; p2[1] = A1.y * inv9;
        float* p3 = sh + (96 + lane) * 132 + (j << 1);    // py1, c=lane+32
        p3[0] = A1.z * inv9; p3[1] = A1.w * inv9;
    }
    __syncthreads();

    // Coalesced store: row r = py*64+c -> out[b][c][2u+py][2v0 .. 2v0+127]
    int r   = threadIdx.x >> 1;
    int seg = threadIdx.x & 1;
    int py  = r >> 6;
    int c   = r & 63;
    float*       orow = out + (((size_t)(b * NC1 + c)) << 16)
                      + ((2 * u + py) << 8) + (v0 << 1) + (seg << 6);
    const float* srow = sh + r * 132 + (seg << 6);
#pragma unroll
    for (int i = 0; i < 16; i++)
        *(float4*)(orow + (i << 2)) = *(const float4*)(srow + (i << 2));
}

// ---------------------------------------------------------------------------
extern "C" void kernel_launch(void* const* d_in, const int* in_sizes, int n_in,
                              void* d_out, int out_size) {
    const float* lv1 = nullptr;   // 8388608
    const float* lv2 = nullptr;   // 4194304
    const int*   hix = nullptr;   // 32768
    for (int i = 0; i < n_in; i++) {
        if (in_sizes[i] == 8388608)      lv1 = (const float*)d_in[i];
        else if (in_sizes[i] == 4194304) lv2 = (const float*)d_in[i];
        else if (in_sizes[i] == 32768)   hix = (const int*)d_in[i];
    }
    float* out = (float*)d_out;

    cudaFuncSetAttribute(k_lv2, cudaFuncAttributeMaxDynamicSharedMemorySize, 131072);
    cudaFuncSetAttribute(k_lv1, cudaFuncAttributeMaxDynamicSharedMemorySize, 67584);

    k_detect<<<1, 256>>>(hix);
    k_extract<<<128, 256>>>(hix);
    k_blk<<<1024, 256>>>(lv1);
    k_lv2<<<128, 512, 131072>>>(lv2, out);
    k_lv1<<<512, 256, 67584>>>(out + OUT_LV2_ELEMS);
}

// round 3
// speedup vs baseline: 1.2448x; 1.2448x over previous
#include <cuda_runtime.h>
#include <cstdint>

#define Hh 128
#define Ww 128
#define LL 16384          // H*W
#define NB 2
#define NC1 64
#define NC2 128
#define OUT_LV2_ELEMS 4194304

// Scratch
__device__ int    g_idx[NB * LL];                    // 128 KB
__device__ int    g_stride;                          // 1 = int32 input, 2 = int64 input
__device__ float4 g_blk2[(size_t)NB * LL * NC1];     // 33.5 MB: [b][cell][c] -> 2x2 block

// ---------------------------------------------------------------------------
// Index dtype detection + extraction (jax may canonicalize int64->int32).
// ---------------------------------------------------------------------------
__global__ void k_detect(const int* __restrict__ hw) {
    __shared__ int s_or;
    if (threadIdx.x == 0) s_or = 0;
    __syncthreads();
    int acc = 0;
    for (int i = threadIdx.x; i < 2048; i += blockDim.x) acc |= hw[2 * i + 1];
    if (acc) atomicOr(&s_or, 1);
    __syncthreads();
    if (threadIdx.x == 0) g_stride = s_or ? 1 : 2;
}

__global__ void k_extract(const int* __restrict__ hw) {
    int stride = g_stride;
    int i = blockIdx.x * blockDim.x + threadIdx.x;
    if (i < NB * LL) g_idx[i] = hw[i * stride];
}

// ---------------------------------------------------------------------------
// k_blk: space-to-depth transpose of lv1 into channel-innermost blocked layout.
// g_blk2[(b*LL + cell)*64 + c] = float4{p00,p01,p10,p11} of channel c.
// SMEM staging: float4 rows of stride 33 (33 mod 8 = 1 -> LDS.128 across c is
// conflict-free); read-phase stores vectorized to STS.64 (<=2-way).
// ---------------------------------------------------------------------------
__global__ void k_blk(const float* __restrict__ lv1) {
    __shared__ float4 s4[64 * 33];
    float2* s2 = (float2*)s4;                 // row stride 66 float2 per c
    int bid = blockIdx.x;                     // 2*128*4 = 1024
    int vt = bid & 3;
    int mh = (bid >> 2) & 127;
    int b  = bid >> 9;
    int v0 = vt << 5;

    // Read phase: 2048 float4 (64 ch x 2 rows x 64 cols), coalesced.
#pragma unroll
    for (int k = 0; k < 8; k++) {
        int j  = threadIdx.x + (k << 8);
        int c  = j >> 5;
        int dy = (j >> 4) & 1;
        int x4 = j & 15;
        const float4 val = *(const float4*)(lv1 + (((size_t)(b * NC1 + c)) << 16)
                                            + ((2 * mh + dy) << 8) + (v0 << 1) + (x4 << 2));
        int vl0 = x4 << 1;                    // covers cells vl0, vl0+1
        s2[c * 66 + (vl0 << 1) + dy]     = make_float2(val.x, val.y);
        s2[c * 66 + (vl0 << 1) + 2 + dy] = make_float2(val.z, val.w);
    }
    __syncthreads();

    // Write phase: g_blk2[b][mh*128 + v0 + vl][c], lanes over c -> 512B/warp.
    float4* dst = g_blk2 + ((size_t)b * LL + (mh << 7) + v0) * 64;
#pragma unroll
    for (int k = 0; k < 8; k++) {
        int j  = threadIdx.x + (k << 8);
        int vl = j >> 6;
        int c  = j & 63;
        dst[(size_t)vl * 64 + c] = s4[c * 33 + vl];
    }
}

// ---------------------------------------------------------------------------
// k_lv2: plane-resident SMEM gather (2 channels/block, 128KB), now with 1024
// threads/block (32 warps/SM) and 2-pixel manual unroll for latency hiding.
// ---------------------------------------------------------------------------
__device__ __forceinline__ void lv2_pixel(const int* __restrict__ idxb,
                                          const float2* __restrict__ s_plane,
                                          int p, float& a0, float& a1) {
    int y = p >> 7, x = p & 127;
#pragma unroll
    for (int dy = -1; dy <= 1; dy++) {
#pragma unroll
        for (int dx = -1; dx <= 1; dx++) {
            int oy = y - dy, ox = x - dx;
            if ((unsigned)oy < Hh && (unsigned)ox < Ww) {
                int m  = idxb[(oy << 7) + ox];
                int sr = (m >> 7)  + dy;
                int sc = (m & 127) + dx;
                if ((unsigned)sr < Hh && (unsigned)sc < Ww) {
                    float2 v = s_plane[(sr << 7) + sc];
                    a0 += v.x; a1 += v.y;
                }
            }
        }
    }
}

__global__ void k_lv2(const float* __restrict__ lv2, float* __restrict__ out) {
    extern __shared__ float2 s_plane[];              // 16384 float2 = 128 KB
    int bcp = blockIdx.x;
    int cp  = bcp & 63;
    int b   = bcp >> 6;
    const float* base0 = lv2 + ((size_t)(b * NC2 + cp * 2) << 14);
    for (int i = threadIdx.x; i < LL; i += blockDim.x)
        s_plane[i] = make_float2(base0[i], base0[i + LL]);
    __syncthreads();

    const int* idxb = g_idx + (b << 14);
    float* out0 = out + ((size_t)(b * NC2 + cp * 2) << 14);
    const float inv9 = 1.0f / 9.0f;

#pragma unroll
    for (int it = 0; it < 8; it++) {
        int p1 = threadIdx.x + (it << 11);           // it*2048
        int p2 = p1 + 1024;
        float a0 = 0.f, a1 = 0.f, b0 = 0.f, b1 = 0.f;
        lv2_pixel(idxb, s_plane, p1, a0, a1);
        lv2_pixel(idxb, s_plane, p2, b0, b1);
        out0[p1]      = a0 * inv9;
        out0[p1 + LL] = a1 * inv9;
        out0[p2]      = b0 * inv9;
        out0[p2 + LL] = b1 * inv9;
    }
}

// ---------------------------------------------------------------------------
// k_lv1: warp-per-cell gather, lanes = channels (coalesced 512B LDG.128 taps).
// Output staged in SMEM with float2 row stride 65 (<=2-way banks), copied out
// warp-per-row with coalesced 256B stores.
// ---------------------------------------------------------------------------
__global__ void k_lv1(float* __restrict__ out) {
    extern __shared__ float2 sh2[];           // 128 rows x 65 float2 = 66560 B
    int bid = blockIdx.x;                     // 2*128*2 = 512
    int vt = bid & 1;
    int u  = (bid >> 1) & 127;
    int b  = bid >> 8;
    int v0 = vt << 6;
    int w    = threadIdx.x >> 5;
    int lane = threadIdx.x & 31;
    const int*    idxb = g_idx + (b << 14);
    const float4* blkb = g_blk2 + (((size_t)b) << 14) * 64;
    const float inv9 = 1.0f / 9.0f;

#pragma unroll 2
    for (int jj = 0; jj < 8; jj++) {
        int j = (w << 3) + jj;                // local cell 0..63
        int v = v0 + j;
        float4 A0 = make_float4(0.f, 0.f, 0.f, 0.f);
        float4 A1 = make_float4(0.f, 0.f, 0.f, 0.f);
#pragma unroll
        for (int dy = -1; dy <= 1; dy++) {
#pragma unroll
            for (int dx = -1; dx <= 1; dx++) {
                int ou = u - dy, ov = v - dx;
                if ((unsigned)ou < Hh && (unsigned)ov < Ww) {
                    int m   = idxb[(ou << 7) + ov];          // uniform across warp
                    int shh = (m >> 7)  + dy;
                    int sww = (m & 127) + dx;
                    if ((unsigned)shh < Hh && (unsigned)sww < Ww) {
                        const float4* q = blkb + (((size_t)((shh << 7) + sww)) << 6);
                        float4 q0 = q[lane];
                        float4 q1 = q[lane + 32];
                        A0.x += q0.x; A0.y += q0.y; A0.z += q0.z; A0.w += q0.w;
                        A1.x += q1.x; A1.y += q1.y; A1.z += q1.z; A1.w += q1.w;
                    }
                }
            }
        }
        // rows r = py*64 + c, row stride 65 float2; column j = one float2
        sh2[(lane       ) * 65 + j] = make_float2(A0.x * inv9, A0.y * inv9); // py0, c=lane
        sh2[(64  + lane ) * 65 + j] = make_float2(A0.z * inv9, A0.w * inv9); // py1, c=lane
        sh2[(lane + 32  ) * 65 + j] = make_float2(A1.x * inv9, A1.y * inv9); // py0, c=lane+32
        sh2[(96  + lane ) * 65 + j] = make_float2(A1.z * inv9, A1.w * inv9); // py1, c=lane+32
    }
    __syncthreads();

    // Copy-out: warp per row; lanes cover the 128-float row in 2 coalesced
    // 256B STG.64 bursts. out[b][c][2u+py][2v0 .. 2v0+127]
    for (int r = w; r < 128; r += 8) {
        int py = r >> 6;
        int c  = r & 63;
        float2* orow = (float2*)(out + (((size_t)(b * NC1 + c)) << 16)
                                 + ((2 * u + py) << 8) + (v0 << 1));
        const float2* srow = sh2 + r * 65;
        orow[lane]      = srow[lane];
        orow[lane + 32] = srow[lane + 32];
    }
}

// ---------------------------------------------------------------------------
extern "C" void kernel_launch(void* const* d_in, const int* in_sizes, int n_in,
                              void* d_out, int out_size) {
    const float* lv1 = nullptr;   // 8388608
    const float* lv2 = nullptr;   // 4194304
    const int*   hix = nullptr;   // 32768
    for (int i = 0; i < n_in; i++) {
        if (in_sizes[i] == 8388608)      lv1 = (const float*)d_in[i];
        else if (in_sizes[i] == 4194304) lv2 = (const float*)d_in[i];
        else if (in_sizes[i] == 32768)   hix = (const int*)d_in[i];
    }
    float* out = (float*)d_out;

    cudaFuncSetAttribute(k_lv2, cudaFuncAttributeMaxDynamicSharedMemorySize, 131072);
    cudaFuncSetAttribute(k_lv1, cudaFuncAttributeMaxDynamicSharedMemorySize, 66560);

    k_detect<<<1, 256>>>(hix);
    k_extract<<<128, 256>>>(hix);
    k_blk<<<1024, 256>>>(lv1);
    k_lv2<<<128, 1024, 131072>>>(lv2, out);
    k_lv1<<<512, 256, 66560>>>(out + OUT_LV2_ELEMS);
}

// round 4
// speedup vs baseline: 1.7976x; 1.4440x over previous
#include <cuda_runtime.h>
#include <cstdint>

#define Hh 128
#define Ww 128
#define LL 16384          // H*W
#define NB 2
#define NC1 64
#define NC2 128
#define OUT_LV2_ELEMS 4194304

// Scratch
__device__ int    g_idx[NB * LL];                    // 128 KB
__device__ float4 g_blk2[(size_t)NB * LL * NC1];     // 33.5 MB: [b][cell][c] -> 2x2 block

// ---------------------------------------------------------------------------
// k_idx: detect index dtype (jax may canonicalize int64->int32) and extract
// low 32-bit words. Each block redundantly samples 2048 odd words (values are
// < 16384, so an int64 buffer has all-zero odd words) then extracts its slice.
// ---------------------------------------------------------------------------
__global__ void k_idx(const int* __restrict__ hw) {
    __shared__ int s_or;
    if (threadIdx.x == 0) s_or = 0;
    __syncthreads();
    int acc = 0;
#pragma unroll
    for (int k = 0; k < 8; k++) acc |= hw[2 * (threadIdx.x + (k << 8)) + 1];
    if (acc) atomicOr(&s_or, 1);
    __syncthreads();
    int stride = s_or ? 1 : 2;
    int i = blockIdx.x * blockDim.x + threadIdx.x;
    g_idx[i] = hw[i * stride];
}

// ---------------------------------------------------------------------------
// k_blk: space-to-depth transpose of lv1 into channel-innermost blocked layout.
// g_blk2[(b*LL + cell)*64 + c] = float4{p00,p01,p10,p11} of channel c.
// ---------------------------------------------------------------------------
__global__ void k_blk(const float* __restrict__ lv1) {
    __shared__ float4 s4[64 * 33];
    float2* s2 = (float2*)s4;                 // row stride 66 float2 per c
    int bid = blockIdx.x;                     // 2*128*4 = 1024
    int vt = bid & 3;
    int mh = (bid >> 2) & 127;
    int b  = bid >> 9;
    int v0 = vt << 5;

#pragma unroll
    for (int k = 0; k < 8; k++) {
        int j  = threadIdx.x + (k << 8);
        int c  = j >> 5;
        int dy = (j >> 4) & 1;
        int x4 = j & 15;
        const float4 val = *(const float4*)(lv1 + (((size_t)(b * NC1 + c)) << 16)
                                            + ((2 * mh + dy) << 8) + (v0 << 1) + (x4 << 2));
        int vl0 = x4 << 1;
        s2[c * 66 + (vl0 << 1) + dy]     = make_float2(val.x, val.y);
        s2[c * 66 + (vl0 << 1) + 2 + dy] = make_float2(val.z, val.w);
    }
    __syncthreads();

    float4* dst = g_blk2 + ((size_t)b * LL + (mh << 7) + v0) * 64;
#pragma unroll
    for (int k = 0; k < 8; k++) {
        int j  = threadIdx.x + (k << 8);
        int vl = j >> 6;
        int c  = j & 63;
        dst[(size_t)vl * 64 + c] = s4[c * 33 + vl];
    }
}

// ---------------------------------------------------------------------------
// k_lv2: plane-resident SMEM gather (2 channels/block, 128KB), 1024 threads.
// ---------------------------------------------------------------------------
__device__ __forceinline__ void lv2_pixel(const int* __restrict__ idxb,
                                          const float2* __restrict__ s_plane,
                                          int p, float& a0, float& a1) {
    int y = p >> 7, x = p & 127;
#pragma unroll
    for (int dy = -1; dy <= 1; dy++) {
#pragma unroll
        for (int dx = -1; dx <= 1; dx++) {
            int oy = y - dy, ox = x - dx;
            if ((unsigned)oy < Hh && (unsigned)ox < Ww) {
                int m  = idxb[(oy << 7) + ox];
                int sr = (m >> 7)  + dy;
                int sc = (m & 127) + dx;
                if ((unsigned)sr < Hh && (unsigned)sc < Ww) {
                    float2 v = s_plane[(sr << 7) + sc];
                    a0 += v.x; a1 += v.y;
                }
            }
        }
    }
}

__global__ void k_lv2(const float* __restrict__ lv2, float* __restrict__ out) {
    extern __shared__ float2 s_plane[];              // 16384 float2 = 128 KB
    int bcp = blockIdx.x;
    int cp  = bcp & 63;
    int b   = bcp >> 6;
    const float* base0 = lv2 + ((size_t)(b * NC2 + cp * 2) << 14);
    for (int i = threadIdx.x; i < LL; i += blockDim.x)
        s_plane[i] = make_float2(base0[i], base0[i + LL]);
    __syncthreads();

    const int* idxb = g_idx + (b << 14);
    float* out0 = out + ((size_t)(b * NC2 + cp * 2) << 14);
    const float inv9 = 1.0f / 9.0f;

#pragma unroll
    for (int it = 0; it < 8; it++) {
        int p1 = threadIdx.x + (it << 11);
        int p2 = p1 + 1024;
        float a0 = 0.f, a1 = 0.f, b0 = 0.f, b1 = 0.f;
        lv2_pixel(idxb, s_plane, p1, a0, a1);
        lv2_pixel(idxb, s_plane, p2, b0, b1);
        out0[p1]      = a0 * inv9;
        out0[p1 + LL] = a1 * inv9;
        out0[p2]      = b0 * inv9;
        out0[p2 + LL] = b1 * inv9;
    }
}

// ---------------------------------------------------------------------------
// k_lv1: warp-per-cell gather, lanes = 32 channels (one coalesced 512B
// LDG.128 per tap). 9 independent predicated loads per cell -> sum tree,
// so ~9 loads in flight per warp (L2-throughput bound, not latency bound).
// Output staged in 33.3KB SMEM (3 blocks/SM) -> coalesced 256B stores.
// Grid axes: (b, u, vtile of 64 cells, channel-half).
// ---------------------------------------------------------------------------
__global__ void __launch_bounds__(256, 3) k_lv1(float* __restrict__ out) {
    extern __shared__ float2 sh2[];           // 64 rows x 65 float2 = 33280 B
    int bid  = blockIdx.x;                    // 2*128*2*2 = 1024
    int half = bid & 1;
    int vt   = (bid >> 1) & 1;
    int u    = (bid >> 2) & 127;
    int b    = bid >> 9;
    int v0   = vt << 6;
    int w    = threadIdx.x >> 5;
    int lane = threadIdx.x & 31;
    const int*    idxb = g_idx + (b << 14);
    const float4* blkb = g_blk2 + ((((size_t)b) << 14) << 6) + (half << 5) + lane;
    const float inv9 = 1.0f / 9.0f;

#pragma unroll
    for (int jj = 0; jj < 8; jj++) {
        int j = (w << 3) + jj;                // local cell 0..63
        int v = v0 + j;
        float4 t[9];
#pragma unroll
        for (int dy = -1; dy <= 1; dy++) {
#pragma unroll
            for (int dx = -1; dx <= 1; dx++) {
                int ti = (dy + 1) * 3 + (dx + 1);
                int ou = u - dy, ov = v - dx;
                bool vo = ((unsigned)ou < Hh) & ((unsigned)ov < Ww);
                int m   = idxb[vo ? (ou << 7) + ov : 0];     // warp-uniform
                int shh = (m >> 7)  + dy;
                int sww = (m & 127) + dx;
                bool ok = vo & ((unsigned)shh < Hh) & ((unsigned)sww < Ww);
                if (ok)
                    t[ti] = blkb[((size_t)((shh << 7) + sww)) << 6];
                else
                    t[ti] = make_float4(0.f, 0.f, 0.f, 0.f);
            }
        }
        // sum tree
        float4 s01 = make_float4(t[0].x + t[1].x, t[0].y + t[1].y, t[0].z + t[1].z, t[0].w + t[1].w);
        float4 s23 = make_float4(t[2].x + t[3].x, t[2].y + t[3].y, t[2].z + t[3].z, t[2].w + t[3].w);
        float4 s45 = make_float4(t[4].x + t[5].x, t[4].y + t[5].y, t[4].z + t[5].z, t[4].w + t[5].w);
        float4 s67 = make_float4(t[6].x + t[7].x, t[6].y + t[7].y, t[6].z + t[7].z, t[6].w + t[7].w);
        float4 A;
        A.x = (s01.x + s23.x) + (s45.x + s67.x) + t[8].x;
        A.y = (s01.y + s23.y) + (s45.y + s67.y) + t[8].y;
        A.z = (s01.z + s23.z) + (s45.z + s67.z) + t[8].z;
        A.w = (s01.w + s23.w) + (s45.w + s67.w) + t[8].w;
        // stage: rows r = py*32 + c_local (stride 65 f2), col j
        sh2[lane * 65 + j]        = make_float2(A.x * inv9, A.y * inv9);
        sh2[(32 + lane) * 65 + j] = make_float2(A.z * inv9, A.w * inv9);
    }
    __syncthreads();

    // Copy-out: warp per row (64 rows), coalesced 256B float2 stores.
    // out[b][half*32 + c][2u+py][2*v0 .. 2*v0+127]
    for (int r = w; r < 64; r += 8) {
        int py = r >> 5;
        int c  = r & 31;
        float2* orow = (float2*)(out + (((size_t)(b * NC1 + (half << 5) + c)) << 16)
                                 + ((2 * u + py) << 8) + (v0 << 1));
        const float2* srow = sh2 + r * 65;
        orow[lane]      = srow[lane];
        orow[lane + 32] = srow[lane + 32];
    }
}

// ---------------------------------------------------------------------------
extern "C" void kernel_launch(void* const* d_in, const int* in_sizes, int n_in,
                              void* d_out, int out_size) {
    const float* lv1 = nullptr;   // 8388608
    const float* lv2 = nullptr;   // 4194304
    const int*   hix = nullptr;   // 32768
    for (int i = 0; i < n_in; i++) {
        if (in_sizes[i] == 8388608)      lv1 = (const float*)d_in[i];
        else if (in_sizes[i] == 4194304) lv2 = (const float*)d_in[i];
        else if (in_sizes[i] == 32768)   hix = (const int*)d_in[i];
    }
    float* out = (float*)d_out;

    cudaFuncSetAttribute(k_lv2, cudaFuncAttributeMaxDynamicSharedMemorySize, 131072);
    cudaFuncSetAttribute(k_lv1, cudaFuncAttributeMaxDynamicSharedMemorySize, 33280);

    k_idx<<<128, 256>>>(hix);
    k_blk<<<1024, 256>>>(lv1);
    k_lv2<<<128, 1024, 131072>>>(lv2, out);
    k_lv1<<<1024, 256, 33280>>>(out + OUT_LV2_ELEMS);
}